// round 10
// baseline (speedup 1.0000x reference)
#include <cuda_runtime.h>
#include <math.h>

#define DIM   1024
#define NC    8
#define NPER  4096
#define QDIM  128
#define TOPK  128
#define HBITS 14
#define HBINS (1 << HBITS)      // 16384 bins per cluster
#define CANDMAX 640

// Scratch (no allocations allowed -> __device__ globals)
__device__ float g_w[NC][DIM];                   // q_w^T @ qk per cluster
__device__ float g_b0[NC];                       // q_b . qk
__device__ unsigned long long g_keys[NC][NPER];  // (desc-map(score)<<32)|idx
__device__ unsigned g_hist[NC][HBINS];           // 14-bit key-prefix histogram
__device__ int   g_topidx[NC][TOPK];             // sorted top-k indices
__device__ float g_gvec[NC][DIM];                // sum_n e^{s_n} feats[n]
__device__ float g_Z[NC];                        // sum_n e^{s_n}

// ---------------------------------------------------------------------------
// No-op kernel: capture alignment. [noop, noop, prep, fused <- 4th, ...]
// ---------------------------------------------------------------------------
__global__ void noop_kernel() {}

// ---------------------------------------------------------------------------
// Kernel A: per-cluster qk = key@q_w^T + q_b ; w = q_w^T @ qk ; b0 = q_b.qk
// Also zeroes g_gvec / g_Z / g_hist. grid = NC, block = 1024. UNCHANGED.
// ---------------------------------------------------------------------------
__global__ __launch_bounds__(1024) void prep_kernel(const float* __restrict__ key_feats,
                                                    const float* __restrict__ q_w,
                                                    const float* __restrict__ q_b) {
    __shared__ __align__(16) float s_qk[QDIM];
    __shared__ float red[4];
    int c = blockIdx.x;
    int t = threadIdx.x;
    int warp = t >> 5, lane = t & 31;

    g_gvec[c][t] = 0.f;          // t covers all DIM=1024
    if (t == 0) g_Z[c] = 0.f;

    // zero this cluster's histogram (16384 bins = 4096 uint4)
    {
        uint4* hp = (uint4*)g_hist[c];
        uint4 z = make_uint4(0u, 0u, 0u, 0u);
        #pragma unroll
        for (int i = 0; i < 4; i++) hp[t + i * 1024] = z;
    }

    const float4* kr = (const float4*)(key_feats + (size_t)c * DIM);
    #pragma unroll
    for (int rr = 0; rr < 4; rr++) {
        int q = warp + rr * 32;
        const float4* qr = (const float4*)(q_w + (size_t)q * DIM);
        float a = 0.f;
        #pragma unroll
        for (int k = 0; k < 8; k++) {
            float4 x = qr[lane + k * 32], y = kr[lane + k * 32];
            a += x.x * y.x + x.y * y.y + x.z * y.z + x.w * y.w;
        }
        #pragma unroll
        for (int o = 16; o > 0; o >>= 1)
            a += __shfl_xor_sync(0xffffffffu, a, o);
        if (lane == 0) s_qk[q] = a + q_b[q];
    }
    __syncthreads();

    float wacc = 0.f;
    #pragma unroll 16
    for (int q = 0; q < QDIM; q++)
        wacc += s_qk[q] * q_w[(size_t)q * DIM + t];
    g_w[c][t] = wacc;

    if (t < QDIM) {
        float p = s_qk[t] * q_b[t];
        #pragma unroll
        for (int o = 16; o > 0; o >>= 1)
            p += __shfl_xor_sync(0xffffffffu, p, o);
        if (lane == 0) red[warp] = p;
    }
    __syncthreads();
    if (t == 0) g_b0[c] = red[0] + red[1] + red[2] + red[3];
}

// ---------------------------------------------------------------------------
// Kernel B (REWORKED): warp-PAIR per row to halve register pressure.
// Block = 512 threads (16 warps). Warps (2j,2j+1) own halves of row j.
// Per lane: f[4] + acc[4] float4 (~32 regs data) -> target 3-4 CTAs/SM.
// 8 stages x 8 rows = 64 rows per block; grid = NC*64 = 512 blocks.
// ---------------------------------------------------------------------------
__global__ __launch_bounds__(512) void fused_pass_kernel(const float* __restrict__ feats) {
    __shared__ __align__(16) float sw[DIM];     // weight vector
    __shared__ __align__(16) float sacc[DIM];   // block accumulator
    __shared__ float part[16];                  // per-warp partial dots
    __shared__ float se[8];                     // exp weights per stage row
    __shared__ float zsh;

    int bid = blockIdx.x;
    int c = bid >> 6;
    int base = (bid & 63) * 64;
    int t = threadIdx.x;
    int warp = t >> 5, lane = t & 31;
    int j = warp >> 1;        // row slot 0..7
    int h = warp & 1;         // column half 0/1

    if (t < 256) {
        ((float4*)sw)[t]   = ((const float4*)(g_w[c]))[t];
        ((float4*)sacc)[t] = make_float4(0.f, 0.f, 0.f, 0.f);
    }
    if (t == 0) zsh = 0.f;
    float b0 = g_b0[c];
    __syncthreads();

    // my half-row base (512 cols = 128 float4), col4 index = h*128 + lane + 32k
    const float4* wr = ((const float4*)sw) + h * 128;

    float4 acc[4];
    #pragma unroll
    for (int k = 0; k < 4; k++) acc[k] = make_float4(0.f, 0.f, 0.f, 0.f);

    for (int st = 0; st < 8; st++) {
        int row = base + st * 8 + j;
        const float4* fr =
            (const float4*)(feats + ((size_t)c * NPER + row) * DIM) + h * 128;

        float4 f[4];
        #pragma unroll
        for (int k = 0; k < 4; k++)
            f[k] = fr[lane + k * 32];

        float d = 0.f;
        #pragma unroll
        for (int k = 0; k < 4; k++) {
            float4 w4 = wr[lane + k * 32];
            d += f[k].x * w4.x + f[k].y * w4.y + f[k].z * w4.z + f[k].w * w4.w;
        }
        #pragma unroll
        for (int o = 16; o > 0; o >>= 1)
            d += __shfl_xor_sync(0xffffffffu, d, o);
        if (lane == 0) part[warp] = d;
        __syncthreads();

        if (h == 0 && lane == 0) {
            float s = (part[2 * j] + part[2 * j + 1] + b0)
                      * 0.08838834764831845f;          // 1/sqrt(128)
            float e = expf(s);                          // |s| small: safe
            se[j] = e;
            int n = row;
            unsigned u = __float_as_uint(s);
            u = (u & 0x80000000u) ? ~u : (u | 0x80000000u);  // ascending map
            unsigned dm = ~u;                                // descending map
            g_keys[c][n] = ((unsigned long long)dm << 32) | (unsigned)n;
            atomicAdd(&g_hist[c][dm >> (32 - HBITS)], 1u);   // spread bins
        }
        __syncthreads();

        float e = se[j];
        #pragma unroll
        for (int k = 0; k < 4; k++) {
            acc[k].x += e * f[k].x; acc[k].y += e * f[k].y;
            acc[k].z += e * f[k].z; acc[k].w += e * f[k].w;
        }
        if (t == 0) {
            float zl = 0.f;
            #pragma unroll
            for (int r = 0; r < 8; r++) zl += se[r];
            zsh += zl;
        }
        __syncthreads();   // protect part/se before next stage overwrites
    }

    // combine: round r -> warps (2r, 2r+1) add their halves (disjoint cols)
    for (int r = 0; r < 8; r++) {
        if (j == r) {
            float4* sa = ((float4*)sacc) + h * 128;
            #pragma unroll
            for (int k = 0; k < 4; k++) {
                float4* p = &sa[lane + k * 32];
                float4 v = *p;
                v.x += acc[k].x; v.y += acc[k].y;
                v.z += acc[k].z; v.w += acc[k].w;
                *p = v;
            }
        }
        __syncthreads();
    }

    // global accumulate: 512 threads x 2 floats = 1024
    atomicAdd(&g_gvec[c][2 * t],     sacc[2 * t]);
    atomicAdd(&g_gvec[c][2 * t + 1], sacc[2 * t + 1]);
    if (t == 0) atomicAdd(&g_Z[c], zsh);
}

// ---------------------------------------------------------------------------
// Kernel C: exact top-128 via precomputed 14-bit histogram. UNCHANGED
// (measured 8.3us).
// ---------------------------------------------------------------------------
__global__ __launch_bounds__(1024) void topk_kernel() {
    __shared__ unsigned warp_tot[32];
    __shared__ unsigned warp_off[32];
    __shared__ unsigned s_B, s_total;
    __shared__ unsigned long long cand[CANDMAX];

    int c = blockIdx.x;
    int t = threadIdx.x;
    int warp = t >> 5, lane = t & 31;

    // ---- 1. histogram scan: find bin B where cumulative count >= 128 ----
    unsigned bins[16];
    {
        const uint4* hp = (const uint4*)g_hist[c];
        #pragma unroll
        for (int i = 0; i < 4; i++) {
            uint4 q = hp[t * 4 + i];
            bins[i * 4 + 0] = q.x; bins[i * 4 + 1] = q.y;
            bins[i * 4 + 2] = q.z; bins[i * 4 + 3] = q.w;
        }
    }
    unsigned loc = 0u;
    #pragma unroll
    for (int i = 0; i < 16; i++) loc += bins[i];

    unsigned incl = loc;
    #pragma unroll
    for (int o = 1; o < 32; o <<= 1) {
        unsigned u = __shfl_up_sync(0xffffffffu, incl, o);
        if (lane >= o) incl += u;
    }
    if (lane == 31) warp_tot[warp] = incl;
    __syncthreads();
    if (warp == 0) {
        unsigned v = warp_tot[lane];
        unsigned i2 = v;
        #pragma unroll
        for (int o = 1; o < 32; o <<= 1) {
            unsigned u = __shfl_up_sync(0xffffffffu, i2, o);
            if (lane >= o) i2 += u;
        }
        warp_off[lane] = i2 - v;   // exclusive per-warp offset
    }
    __syncthreads();

    unsigned texcl = warp_off[warp] + incl - loc;  // excl prefix before my bins
    if (texcl < TOPK && texcl + loc >= TOPK) {     // crossing in my 16 bins
        unsigned run = texcl;
        #pragma unroll
        for (int i = 0; i < 16; i++) {
            run += bins[i];
            if (run >= TOPK) { s_B = (unsigned)(t * 16 + i); s_total = run; break; }
        }
    }
    __syncthreads();
    unsigned B = s_B;

    // ---- 2. compact candidates (prefix <= B) via ballot-scan ----
    unsigned long long key[4];
    bool sel[4];
    unsigned laneoff[4];
    unsigned cnt_w = 0u;
    #pragma unroll
    for (int i = 0; i < 4; i++) {
        key[i] = g_keys[c][t + i * 1024];
        sel[i] = ((unsigned)(key[i] >> (64 - HBITS)) <= B);
        unsigned b = __ballot_sync(0xffffffffu, sel[i]);
        laneoff[i] = cnt_w + __popc(b & ((1u << lane) - 1u));
        cnt_w += __popc(b);
    }
    if (lane == 0) warp_tot[warp] = cnt_w;
    __syncthreads();
    if (warp == 0) {
        unsigned v = warp_tot[lane];
        unsigned i2 = v;
        #pragma unroll
        for (int o = 1; o < 32; o <<= 1) {
            unsigned u = __shfl_up_sync(0xffffffffu, i2, o);
            if (lane >= o) i2 += u;
        }
        warp_off[lane] = i2 - v;
    }
    __syncthreads();
    unsigned cbase = warp_off[warp];
    #pragma unroll
    for (int i = 0; i < 4; i++) {
        if (sel[i]) {
            unsigned p = cbase + laneoff[i];
            if (p < CANDMAX) cand[p] = key[i];
        }
    }
    __syncthreads();

    // ---- 3. rank-by-counting (candidate rank == global rank) ----
    unsigned cnt = s_total < CANDMAX ? s_total : CANDMAX;
    if (t < cnt) {
        unsigned long long mine = cand[t];
        unsigned rank = 0u;
        for (unsigned j = 0; j < cnt; j++)
            rank += (cand[j] < mine) ? 1u : 0u;
        if (rank < TOPK)
            g_topidx[c][rank] = (int)(unsigned)(mine & 0xffffffffu);
    }
}

// ---------------------------------------------------------------------------
// Kernel D (merged gather + fusion), block = 256. UNCHANGED.
// ---------------------------------------------------------------------------
__global__ __launch_bounds__(256) void gather_fusion_kernel(
        const float* __restrict__ feats,
        const float* __restrict__ v_w,
        const float* __restrict__ v_b,
        float* __restrict__ out) {
    __shared__ __align__(16) float sg[DIM];
    int t = threadIdx.x;

    if (blockIdx.x < 1024) {
        int row = blockIdx.x;
        int c = row >> 7, k = row & 127;
        int src = g_topidx[c][k];
        const float4* s =
            (const float4*)(feats + ((size_t)c * NPER + src) * DIM);
        float4* dst = (float4*)(out + (size_t)row * DIM);
        dst[t] = s[t];
        return;
    }

    int bid = blockIdx.x - 1024;   // 0..1023
    int c = bid >> 7;
    int o0 = (bid & 127) * 8;

    float invZ = 1.f / g_Z[c];
    float4 gv = ((const float4*)(g_gvec[c]))[t];
    gv.x *= invZ; gv.y *= invZ; gv.z *= invZ; gv.w *= invZ;
    ((float4*)sg)[t] = gv;
    __syncthreads();

    int warp = t >> 5, lane = t & 31;
    int o = o0 + warp;
    const float4* vr = (const float4*)(v_w + (size_t)o * DIM);
    const float4* gr = (const float4*)sg;
    float acc = 0.f;
    #pragma unroll
    for (int i = 0; i < 8; i++) {
        int idx = lane + i * 32;
        float4 a = vr[idx], b = gr[idx];
        acc += a.x * b.x + a.y * b.y + a.z * b.z + a.w * b.w;
    }
    #pragma unroll
    for (int ofs = 16; ofs > 0; ofs >>= 1)
        acc += __shfl_xor_sync(0xffffffffu, acc, ofs);
    if (lane == 0)
        out[(size_t)1024 * 1024 + (size_t)c * DIM + o] = acc + v_b[o];
}

// ---------------------------------------------------------------------------
extern "C" void kernel_launch(void* const* d_in, const int* in_sizes, int n_in,
                              void* d_out, int out_size) {
    const float* feats     = (const float*)d_in[0];  // [8,4096,1024]
    const float* key_feats = (const float*)d_in[1];  // [8,1,1024]
    const float* q_w       = (const float*)d_in[2];  // [128,1024]
    const float* q_b       = (const float*)d_in[3];  // [128]
    const float* v_w       = (const float*)d_in[4];  // [1024,1024]
    const float* v_b       = (const float*)d_in[5];  // [1024]
    float* out = (float*)d_out;  // selected [1024,1024] then fus [8,1024]

    noop_kernel<<<1, 32>>>();   // capture alignment: fused is 4th launch
    noop_kernel<<<1, 32>>>();
    prep_kernel<<<NC, 1024>>>(key_feats, q_w, q_b);
    fused_pass_kernel<<<NC * 64, 512>>>(feats);   // <- profiled this round
    topk_kernel<<<NC, 1024>>>();
    gather_fusion_kernel<<<2048, 256>>>(feats, v_w, v_b, out);
}